// round 17
// baseline (speedup 1.0000x reference)
#include <cuda_runtime.h>
#include <cuda_fp16.h>
#include <cstdint>

// VQ-VAE bottleneck — 2-pass split-fp16 HMMA distance GEMM + exact rescore,
// B streamed via double-buffered cp.async for 3 CTAs/SM.
// Round 17 = round 16 (139us; latency-bound, warps stalled 94%) with the B
// tile no longer smem-resident: 4 chunks x 16KB (128 codewords each, straight
// copies of pre-swizzled g_cbB1), 2 buffers, prefetch depth 2. smem 101->69.5KB
// -> 3 CTAs/SM (16->24 warps/SM, +50% latency hiding). launch_bounds(256,3).
// Numerics identical to r13-r16 (validated): fp16 2-pass (a1e1+a2e1), scaled
// operands, per-row margin 4*sqrt(Z)*em + 5e-5; flagged rows rescore all 512 k
// bit-exactly: d = RN(RN(Z+B_k) - 2*seqFMA(z,e_k)), (d,k)-lex min.
// Output: straight-through RN(x + RN(q-x)); loss = RN(L + RN(0.25L)), L = SSE/N.

#define CDIM    64
#define KCODES  512
#define HW      4096
#define NELEM   8388608
#define THREADS 256
#define P_CTA   128
#define GRIDSZ  1024
#define QPITCH  65
#define NCHUNK  4              // 128 codewords per chunk

typedef unsigned long long u64;
typedef unsigned int u32;
typedef unsigned short u16;

__device__ float g_loss_sum;
__device__ u32   g_done;
__device__ float g_cbT[CDIM * KCODES];    // transposed codebook [c][k]
__device__ float g_e2[KCODES];            // ||e_k||^2, reference rounding
__device__ u32   g_em2;                   // bits of max_k ||e_k - fp16(e_k)||^2
__device__ uint4 g_cbB1[4096];            // 64KB fp16(1024*e), SW128 smem layout

// smem layout (bytes)
#define OFF_A(h) ((h) * 16384)   // 2 x 128 x 128B (fp16 hi/lo of -32z)
#define OFF_BB   32768           // 2 x 16KB B chunk buffers
#define OFF_E2   65536           // 512 f32
#define OFF_ZS   67584           // 128 f32
#define OFF_KB   68096           // 128 u32
#define OFF_FL   68608           // 128 u32
#define SMEM_SZ  69632
// qsm staging overlays [0, 33280): A0+A1+head of Bbuf0 (all dead post-rescore)

#define SW(o) ((o) ^ (((o) >> 3) & 0x70))

__device__ __forceinline__ u32 smem_u32(const void* p) {
    u32 a; asm("{ .reg .u64 t; cvta.to.shared.u64 t, %1; cvt.u32.u64 %0, t; }" : "=r"(a) : "l"(p));
    return a;
}
__device__ __forceinline__ void cp_async16(u32 dst, const void* src) {
    asm volatile("cp.async.cg.shared.global [%0], [%1], 16;"
                 :: "r"(dst), "l"(src) : "memory");
}
__device__ __forceinline__ void ldsm4(u32 addr, u32& r0, u32& r1, u32& r2, u32& r3) {
    asm volatile("ldmatrix.sync.aligned.m8n8.x4.shared.b16 {%0,%1,%2,%3}, [%4];"
                 : "=r"(r0), "=r"(r1), "=r"(r2), "=r"(r3) : "r"(addr));
}
__device__ __forceinline__ void mma_f16(float* d, const u32* a, u32 b0, u32 b1) {
    asm volatile("mma.sync.aligned.m16n8k16.row.col.f32.f16.f16.f32 "
                 "{%0,%1,%2,%3}, {%4,%5,%6,%7}, {%8,%9}, {%0,%1,%2,%3};"
                 : "+f"(d[0]), "+f"(d[1]), "+f"(d[2]), "+f"(d[3])
                 : "r"(a[0]), "r"(a[1]), "r"(a[2]), "r"(a[3]), "r"(b0), "r"(b1));
}
__device__ __forceinline__ float embed(float s, int k) {
    return __uint_as_float((__float_as_uint(s) & ~511u) | (u32)k);
}
__device__ __forceinline__ void upd2(float& m1, float& m2, float v) {
    float hi = fmaxf(m1, v);
    m1 = fminf(m1, v);
    m2 = fminf(m2, hi);
}

// ---- prep: codebook-derived tables (idempotent across graph replays) ----
__global__ void vq_prep_kernel(const float* __restrict__ cb) {
    int i = blockIdx.x * blockDim.x + threadIdx.x;     // 0..32767
    int k = i >> 6, c = i & 63;
    float e = cb[i];                                    // coalesced
    g_cbT[c * KCODES + k] = e;                          // bit-exact transpose
    __half e1 = __float2half_rn(e * 1024.0f);           // scaled: all normal
    u32 o = SW((u32)(k * 128 + c * 2)) >> 1;            // u16 index, smem layout
    ((u16*)g_cbB1)[o] = *(u16*)&e1;
    if (i < KCODES) {                                   // ||e_i||^2 ref order + residual
        const float* ek = cb + i * CDIM;
        float s = 0.0f, r2 = 0.0f;
        #pragma unroll
        for (int cc = 0; cc < CDIM; cc++) {
            float ev = ek[cc];
            s = __fadd_rn(s, __fmul_rn(ev, ev));
            float eh = __half2float(__float2half_rn(ev * 1024.0f)) * 0.0009765625f;
            float r  = ev - eh;
            r2 += r * r;
        }
        g_e2[i] = s;
        atomicMax(&g_em2, __float_as_uint(r2));         // r2 >= 0: bits monotone
    }
}

extern __shared__ char smc[];

__global__ __launch_bounds__(THREADS, 3)
void vq_main_kernel(const float* __restrict__ x,
                    const float* __restrict__ cb,
                    float* __restrict__ out,
                    int loss_idx) {
    const u32 sb   = smem_u32(smc);
    const int tid  = threadIdx.x;
    const int w    = tid >> 5;
    const int lane = tid & 31;

    float* e2s = (float*)(smc + OFF_E2);
    float* Zs  = (float*)(smc + OFF_ZS);
    u32*   kbs = (u32*)(smc + OFF_KB);
    u32*   fls = (u32*)(smc + OFF_FL);
    float* qsm = (float*)smc;                // staging overlay, post-rescore

    const int b   = blockIdx.x >> 5;
    const int hw0 = (blockIdx.x & 31) * P_CTA;
    const float* xrow = x + (size_t)b * CDIM * HW + hw0;

    // ---- fused prologue, warp-specialized ----
    if (tid < P_CTA) {
        // threads 0-127: load x once per element (c ascending, ref order):
        // fp16 split A halves + Z.
        const int p = tid;
        const float* xp = xrow + p;
        float s = 0.0f;
        #pragma unroll 8
        for (int c = 0; c < CDIM; c++) {
            float v = __ldg(xp + (size_t)c * HW);
            s = __fadd_rn(s, __fmul_rn(v, v));          // ref-order Z chain
            float a = -32.0f * v;                       // exact
            __half a1 = __float2half_rn(a);
            __half a2 = __float2half_rn(__fadd_rn(a, -__half2float(a1)));
            u32 o = SW((u32)(p * 128 + c * 2));
            *(__half*)(smc + OFF_A(0) + o) = a1;
            *(__half*)(smc + OFF_A(1) + o) = a2;
        }
        Zs[p] = s;
    } else {
        // threads 128-255: prefetch B chunks 0 and 1 (16KB each), depth 2
        int t = tid - 128;
        #pragma unroll
        for (int ch = 0; ch < 2; ch++) {
            const uint4* src = g_cbB1 + ch * 1024;
            u32 dst = sb + OFF_BB + ch * 16384;
            #pragma unroll
            for (int i = t; i < 1024; i += 128)
                cp_async16(dst + i * 16, src + i);
            asm volatile("cp.async.commit_group;" ::: "memory");
        }
    }
    for (int k = tid; k < KCODES; k += THREADS) e2s[k] = g_e2[k];

    // ---- A fragments: 2 halves x 4 k-steps ----
    const int m_base = w * 16;
    const int g      = lane >> 2;
    const int t4     = lane & 3;
    const int b_r    = (lane & 7) + ((lane >> 4) << 3);
    const int b_c    = ((lane >> 3) & 1) << 3;
    const u32 bxm    = (u32)((b_r & 7) << 4);
    const float UNSC = 0.00006103515625f;    // 2^-14 (a*16, e*1024)

    __syncthreads();    // A tiles + Zs visible

    u32 afr[2][4][4];
    {
        int a_r = lane & 15, a_c8 = (lane >> 4) << 3;
        u32 xm  = (u32)((a_r & 7) << 4);
        #pragma unroll
        for (int h = 0; h < 2; h++) {
            u32 lin = sb + OFF_A(h) + (u32)((m_base + a_r) * 128 + a_c8 * 2);
            #pragma unroll
            for (int ks = 0; ks < 4; ks++)
                ldsm4((lin + ks * 32) ^ xm,
                      afr[h][ks][0], afr[h][ks][1], afr[h][ks][2], afr[h][ks][3]);
        }
    }

    float mA1 = 1e30f, mA2 = 1e30f;      // row m_base+g   (embedded s values)
    float mB1 = 1e30f, mB2 = 1e30f;      // row m_base+g+8

    // ---- chunked mainloop: 4 chunks x 128 codewords, double-buffered ----
    #pragma unroll 1
    for (int chk = 0; chk < NCHUNK; chk++) {
        // chunk chk's cp.async group must have landed (<=1 newer pending)
        asm volatile("cp.async.wait_group 1;" ::: "memory");
        __syncthreads();

        const u32 bufb = sb + OFF_BB + (u32)((chk & 1) * 16384);
        const u32 blin = bufb + (u32)(b_r * 128 + b_c * 2);

        #pragma unroll
        for (int nc = 0; nc < 4; nc++) {     // 32 codewords per nc
            float acc[4][4];
            #pragma unroll
            for (int i = 0; i < 4; i++)
                #pragma unroll
                for (int j = 0; j < 4; j++) acc[i][j] = 0.0f;

            #pragma unroll
            for (int ks = 0; ks < 4; ks++) {
                u32 off0 = (u32)(nc * 4096 + ks * 32);
                u32 c0, c1, c2, c3, d0, d1, d2, d3;
                ldsm4((blin + off0) ^ bxm,        c0, c1, c2, c3);
                ldsm4((blin + off0 + 2048) ^ bxm, d0, d1, d2, d3);
                mma_f16(acc[0], afr[0][ks], c0, c1);
                mma_f16(acc[1], afr[0][ks], c2, c3);
                mma_f16(acc[2], afr[0][ks], d0, d1);
                mma_f16(acc[3], afr[0][ks], d2, d3);
                mma_f16(acc[0], afr[1][ks], c0, c1);
                mma_f16(acc[1], afr[1][ks], c2, c3);
                mma_f16(acc[2], afr[1][ks], d0, d1);
                mma_f16(acc[3], afr[1][ks], d2, d3);
            }
            #pragma unroll
            for (int pr = 0; pr < 2; pr++) {
                #pragma unroll
                for (int nt = 0; nt < 2; nt++) {
                    int col0 = chk * 128 + nc * 32 + pr * 16 + nt * 8 + 2 * t4;
                    float* a = acc[pr * 2 + nt];
                    float e20 = e2s[col0], e21 = e2s[col0 + 1];
                    upd2(mA1, mA2, embed(__fmaf_rn(a[0], UNSC, e20), col0));
                    upd2(mA1, mA2, embed(__fmaf_rn(a[1], UNSC, e21), col0 + 1));
                    upd2(mB1, mB2, embed(__fmaf_rn(a[2], UNSC, e20), col0));
                    upd2(mB1, mB2, embed(__fmaf_rn(a[3], UNSC, e21), col0 + 1));
                }
            }
        }

        // buffer consumed by all warps; prefetch chunk chk+2 into it
        __syncthreads();
        if (chk + 2 < NCHUNK && tid >= 128) {
            int t = tid - 128;
            const uint4* src = g_cbB1 + (chk + 2) * 1024;
            u32 dst = bufb;
            #pragma unroll
            for (int i = t; i < 1024; i += 128)
                cp_async16(dst + i * 16, src + i);
        }
        if (tid >= 128)
            asm volatile("cp.async.commit_group;" ::: "memory");
    }

    // quad reduce (lanes share a row across t4)
    #pragma unroll
    for (int o = 1; o <= 2; o <<= 1) {
        float a1 = __shfl_xor_sync(0xffffffffu, mA1, o);
        float a2 = __shfl_xor_sync(0xffffffffu, mA2, o);
        float hA = fmaxf(mA1, a1);
        mA1 = fminf(mA1, a1);
        mA2 = fminf(fminf(mA2, a2), hA);
        float b1 = __shfl_xor_sync(0xffffffffu, mB1, o);
        float b2 = __shfl_xor_sync(0xffffffffu, mB2, o);
        float hB = fmaxf(mB1, b1);
        mB1 = fminf(mB1, b1);
        mB2 = fminf(fminf(mB2, b2), hB);
    }
    if (t4 == 0) {
        float em = __fsqrt_rn(__uint_as_float(g_em2));
        int r0 = m_base + g, r1 = m_base + g + 8;
        float mg0 = __fmaf_rn(4.0f * __fsqrt_rn(Zs[r0]), em, 5e-5f);
        float mg1 = __fmaf_rn(4.0f * __fsqrt_rn(Zs[r1]), em, 5e-5f);
        kbs[r0] = __float_as_uint(mA1) & 511u;
        kbs[r1] = __float_as_uint(mB1) & 511u;
        fls[r0] = (mA2 - mA1) < mg0;
        fls[r1] = (mB2 - mB1) < mg1;
    }
    __syncwarp();

    // ---- exact rescore of flagged rows: coalesced via g_cbT[c][k] ----
    for (int r = 0; r < 16; r++) {
        int row = m_base + r;
        if (!fls[row]) continue;
        const float* xz = xrow + row;
        float Zp = Zs[row];
        u64 best = ~0ull;
        #pragma unroll 1
        for (int jj = 0; jj < 4; jj++) {
            int k0 = lane + 128 * jj;                 // + 0,32,64,96 below
            float m0 = 0.f, m1 = 0.f, m2 = 0.f, m3 = 0.f;
            #pragma unroll
            for (int c = 0; c < CDIM; c++) {          // c ascending per chain
                float zc = __ldg(xz + (size_t)c * HW);
                const float* ct = g_cbT + c * KCODES + k0;
                m0 = __fmaf_rn(zc, __ldg(ct),      m0);   // lanes consecutive k
                m1 = __fmaf_rn(zc, __ldg(ct + 32), m1);
                m2 = __fmaf_rn(zc, __ldg(ct + 64), m2);
                m3 = __fmaf_rn(zc, __ldg(ct + 96), m3);
            }
            float mm[4] = { m0, m1, m2, m3 };
            #pragma unroll
            for (int i = 0; i < 4; i++) {
                int k = k0 + 32 * i;
                float tt = __fadd_rn(Zp, e2s[k]);
                float d  = __fadd_rn(tt, -2.0f * mm[i]);
                u64 key = ((u64)__float_as_uint(d) << 32) | (u32)k;   // d > 0
                if (key < best) best = key;
            }
        }
        #pragma unroll
        for (int o = 16; o; o >>= 1) {
            u64 v = __shfl_xor_sync(0xffffffffu, best, o);
            if (v < best) best = v;
        }
        if (lane == 0) kbs[row] = (u32)(best & 0x1FFu);
    }
    __syncthreads();   // kbs final; A tiles + B bufs dead -> qsm may overwrite

    // ---- stage winning codewords into smem, coalesced ----
    for (int i = 0; i < 16; i++) {
        int row = m_base + i;
        const float* src = cb + (size_t)kbs[row] * CDIM;
        qsm[row * QPITCH + lane]      = __ldg(src + lane);
        qsm[row * QPITCH + lane + 32] = __ldg(src + lane + 32);
    }
    __syncthreads();

    // ---- writeback: straight-through RN(x + RN(q-x)) + SSE, q from smem ----
    {
        int p = tid & 127, ch = tid >> 7;
        float* op = out + (size_t)b * CDIM * HW + hw0 + p;
        const float* ip = xrow + p;
        const float* qp = qsm + p * QPITCH;
        float sse = 0.0f;
        #pragma unroll 8
        for (int c = ch * 32; c < ch * 32 + 32; c++) {
            float zv   = __ldg(ip + (size_t)c * HW);
            float qv   = qp[c];                        // LDS, conflict-free
            float diff = __fadd_rn(qv, -zv);
            op[(size_t)c * HW] = __fadd_rn(zv, diff);
            sse = __fadd_rn(sse, __fmul_rn(diff, diff));
        }
        #pragma unroll
        for (int o = 16; o; o >>= 1) sse += __shfl_xor_sync(0xffffffffu, sse, o);
        if (lane == 0) atomicAdd(&g_loss_sum, sse);
    }

    // ---- fused finalize, reset for next graph replay ----
    __syncthreads();
    if (tid == 0) {
        __threadfence();
        u32 done = atomicAdd(&g_done, 1u);
        if (done == gridDim.x - 1) {
            float L = atomicAdd(&g_loss_sum, 0.0f) * (1.0f / (float)NELEM);
            if (loss_idx >= 0)
                out[loss_idx] = __fadd_rn(L, 0.25f * L);
            g_loss_sum = 0.0f;
            g_done     = 0u;
            __threadfence();
        }
    }
}

extern "C" void kernel_launch(void* const* d_in, const int* in_sizes, int n_in,
                              void* d_out, int out_size) {
    const float* x   = (const float*)d_in[0];
    const float* cb  = (const float*)d_in[1];
    float*       out = (float*)d_out;

    cudaFuncSetAttribute(vq_main_kernel,
                         cudaFuncAttributeMaxDynamicSharedMemorySize, SMEM_SZ);
    int loss_idx = (out_size > NELEM) ? (out_size - 1) : -1;
    vq_prep_kernel<<<128, 256>>>(cb);
    vq_main_kernel<<<GRIDSZ, THREADS, SMEM_SZ>>>(x, cb, out, loss_idx);
}